// round 16
// baseline (speedup 1.0000x reference)
#include <cuda_runtime.h>
#include <cstdint>

#define TT 16384
#define CC 1024
#define NROWS 128           // tail rows in stats table (window provably < 25)
#define N_ITERS 30
#define GRID 144            // <= 148 SMs -> one wave, safe software grid barrier
#define NTH 256
#define NB 64               // stage-B blocks (16 u-columns each)

__device__ float g_q[CC];
__device__ float g_u[CC];             // full u (deep fallback)
__device__ float g_patt[NROWS * NB];  // [l][chunk] partial att dots
__device__ float g_av[NROWS];
__device__ int   g_barc[3 * 32];      // [A, B, av]; left 0 after launch

#define SCALE 3.125e-5f     // 0.001 / sqrt(1024)

__device__ __forceinline__ float neg_inf() { return __int_as_float(0xff800000); }

__device__ __forceinline__ void fence_acqrel_gpu() {
    asm volatile("fence.acq_rel.gpu;" ::: "memory");
}

__device__ __forceinline__ void gbar_arrive(int ph) {
    __syncthreads();
    if (threadIdx.x == 0) {
        fence_acqrel_gpu();                  // release: publish prior block writes
        atomicAdd(&g_barc[ph << 5], 1);
    }
}
__device__ __forceinline__ void gbar_wait(int ph, int count) {
    if (threadIdx.x == 0) {
        while (*(volatile int*)&g_barc[ph << 5] < count) { }
        fence_acqrel_gpu();                  // acquire: see published writes
    }
    __syncthreads();
}

__device__ __forceinline__ float wred_sum(float v) {
#pragma unroll
    for (int o = 16; o; o >>= 1) v += __shfl_xor_sync(0xffffffffu, v, o);
    return v;
}

__global__ void __launch_bounds__(NTH, 1)
k_all(const float* __restrict__ x, const float* __restrict__ W,
      const float* __restrict__ alpha, const float* __restrict__ beta,
      float* __restrict__ out)
{
    __shared__ float  sq[CC];                  // q in stage B
    __shared__ float4 bred[8][4];              // B u-reduction across warps
    __shared__ float  su[16];                  // this block's u chunk
    __shared__ float  sS[NROWS + 1], sB[NROWS + 1], sY[NROWS + 1];
    __shared__ float  bu_tab[NROWS + 1];
    __shared__ float  tia[32];
    __shared__ float  fm[8], fs[8], fb[8], fy[8];
    __shared__ float  salpha, sbeta;

    const int b = blockIdx.x, t = threadIdx.x;
    const int lane = t & 31, wid = t >> 5;

    if (b == 0 && t == 0) { salpha = *alpha; sbeta = *beta; }

    // ======== STAGE A: q rows (blocks 0-127) || av tail rows (128-143) ========
    if (b < 128) {
        int i = (b << 3) + wid;                       // W_q row
        const float4* xl4 = (const float4*)(x + (size_t)(TT - 1) * CC);
        const float4* wr4 = (const float4*)(W + (size_t)i * CC);
        float4 xa[8], wa[8];
#pragma unroll
        for (int c = 0; c < 8; c++) xa[c] = xl4[c * 32 + lane];
#pragma unroll
        for (int c = 0; c < 8; c++) wa[c] = wr4[c * 32 + lane];
        float s = 0.f;
#pragma unroll
        for (int c = 0; c < 8; c++)
            s += xa[c].x * wa[c].x + xa[c].y * wa[c].y + xa[c].z * wa[c].z + xa[c].w * wa[c].w;
        s = wred_sum(s);
        if (lane == 0) g_q[i] = s;
    } else {
        int l = ((b - 128) << 3) + wid;               // tail distance
        const float4* xr4 = (const float4*)(x + (size_t)(TT - 1 - l) * CC);
        const float4* wv4 = (const float4*)(W + (size_t)(2 * CC) * CC);
        float4 xa[8], wa[8];
#pragma unroll
        for (int c = 0; c < 8; c++) xa[c] = xr4[c * 32 + lane];
#pragma unroll
        for (int c = 0; c < 8; c++) wa[c] = wv4[c * 32 + lane];
        float s = 0.f;
#pragma unroll
        for (int c = 0; c < 8; c++)
            s += xa[c].x * wa[c].x + xa[c].y * wa[c].y + xa[c].z * wa[c].z + xa[c].w * wa[c].w;
        s = wred_sum(s);
        if (lane == 0) g_av[l] = s;
        gbar_arrive(2);                               // av counter
        return;
    }

    // ---- stage-B prefetch (independent of q), issued BEFORE the barrier ------
    // W_k slice: thread (ig = t>>2, jj4 = t&3) covers rows i = ig + 64*s, cols
    // j0 + 4*jj4 .. +4. Per warp-step: 8 consecutive rows x 64 B contiguous.
    // Also the patt x-slice for this block's chunk (x is read-only input).
    const int j0  = b << 4;                 // 16 columns per B block
    const int ig  = t >> 2;
    const int jj4 = t & 3;
    float4 wkr[16];
    float4 xp0 = make_float4(0.f, 0.f, 0.f, 0.f);
    float4 xp1 = make_float4(0.f, 0.f, 0.f, 0.f);
    if (b < NB) {
        const float* Wk = W + (size_t)CC * CC;
#pragma unroll
        for (int s8 = 0; s8 < 16; s8++)
            wkr[s8] = *(const float4*)(Wk + (size_t)(ig + 64 * s8) * CC + j0 + 4 * jj4);
        int l = t >> 1, h = t & 1;
        const float4* xr = (const float4*)(x + (size_t)(TT - 1 - l) * CC + j0 + 8 * h);
        xp0 = xr[0]; xp1 = xr[1];
    }
    gbar_arrive(0);                         // A counter
    if (b >= NB) return;                    // blocks 64-127 done
    if (b == 0 && t < N_ITERS) tia[t] = 2.0f / (salpha + (float)t);
    gbar_wait(0, 128);

    // ======== STAGE B (blocks 0-63): exact u chunk + partial att ==============
    {
        ((float4*)sq)[t] = ((const float4*)g_q)[t];   // q from L2
        __syncthreads();
        float4 acc = make_float4(0.f, 0.f, 0.f, 0.f);
#pragma unroll
        for (int s8 = 0; s8 < 16; s8++) {
            float qv = sq[ig + 64 * s8];
            acc.x += qv * wkr[s8].x; acc.y += qv * wkr[s8].y;
            acc.z += qv * wkr[s8].z; acc.w += qv * wkr[s8].w;
        }
        // reduce over ig&7 within warp (lane = (ig&7)*4 + jj4)
#pragma unroll
        for (int o = 4; o < 32; o <<= 1) {
            acc.x += __shfl_xor_sync(0xffffffffu, acc.x, o);
            acc.y += __shfl_xor_sync(0xffffffffu, acc.y, o);
            acc.z += __shfl_xor_sync(0xffffffffu, acc.z, o);
            acc.w += __shfl_xor_sync(0xffffffffu, acc.w, o);
        }
        if (lane < 4) bred[wid][lane] = acc;
        __syncthreads();
        if (t < 4) {
            float4 r = bred[0][t];
#pragma unroll
            for (int w = 1; w < 8; w++) {
                float4 p = bred[w][t];
                r.x += p.x; r.y += p.y; r.z += p.z; r.w += p.w;
            }
            ((float4*)su)[t] = r;
            ((float4*)g_u)[(b << 2) + t] = r;         // for the deep fallback
        }
        __syncthreads();

        // partial att: thread (l = t>>1, h = t&1), x slice already in registers
        int l = t >> 1, h = t & 1;
        float4 u0 = ((float4*)su)[2 * h], u1 = ((float4*)su)[2 * h + 1];
        float d = xp0.x * u0.x + xp0.y * u0.y + xp0.z * u0.z + xp0.w * u0.w
                + xp1.x * u1.x + xp1.y * u1.y + xp1.z * u1.z + xp1.w * u1.w;
        d += __shfl_xor_sync(0xffffffffu, d, 1);
        if (h == 0) g_patt[l * NB + b] = d;
    }
    gbar_arrive(1);                         // B counter
    if (b != 0) return;
    gbar_wait(1, NB);
    gbar_wait(2, 16);                       // av ready (long done)
    if (t == 0) { g_barc[0] = 0; g_barc[32] = 0; g_barc[64] = 0; }   // replay-safe

    // ======== STAGE D (block 0): att assembly + stats + serial recurrence =====
    float v0 = (t < NROWS) ? g_av[t] : 0.f;
    float a0 = neg_inf();
    if (t > 0 && t < NROWS) {
        const float4* pr = (const float4*)(g_patt + t * NB);
        float sum = 0.f;
#pragma unroll
        for (int c = 0; c < NB / 4; c++) {
            float4 p = pr[c];
            sum += p.x + p.y + p.z + p.w;
        }
        a0 = sum * SCALE;
    }

    // stats: att in [-1e-3,1e-3] -> exp safe without max shift (shift-invariant)
    if (t < NROWS) {
        float e0 = __expf(a0);                        // a0 = -inf at t=0 -> 0
        float ps = e0, pb = e0 * (float)t, py = e0 * v0;
#pragma unroll
        for (int o = 1; o < 32; o <<= 1) {
            float ts = __shfl_up_sync(0xffffffffu, ps, o);
            float tb = __shfl_up_sync(0xffffffffu, pb, o);
            float ty = __shfl_up_sync(0xffffffffu, py, o);
            if (lane >= o) { ps += ts; pb += tb; py += ty; }
        }
        if (lane == 31) { fs[wid] = ps; fb[wid] = pb; fy[wid] = py; }
        __syncthreads();
        if (t == 0) {
            float cs = 0.f, cb = 0.f, cy = 0.f;
#pragma unroll
            for (int i = 0; i < 4; i++) {
                float ns = fs[i], nb = fb[i], ny = fy[i];
                fs[i] = cs; fb[i] = cb; fy[i] = cy;
                cs += ns; cb += nb; cy += ny;
            }
        }
        __syncthreads();
        ps += fs[wid]; pb += fb[wid]; py += fy[wid];
        sS[t + 1] = ps; sB[t + 1] = pb; sY[t + 1] = py;
        bu_tab[t + 1] = pb / ps;
        if (t == 0) { sS[0] = 0.f; sB[0] = 0.f; sY[0] = 0.f; bu_tab[0] = 0.f; }
    } else {
        __syncthreads(); __syncthreads();
    }
    __syncthreads();

    // ---- fast serial loop: register tia, fully unrolled -----------------------
    float rt[N_ITERS];
#pragma unroll
    for (int i = 0; i < N_ITERS; i++) rt[i] = tia[i];

    float bb = sbeta, k_old = 0.f;
    float s_f = 1.f, ys_f = 0.f;
    bool need_deep = false;
#pragma unroll
    for (int it = 0; it < N_ITERS; it++) {
        float kk = fmaf(bb, rt[it], 2.0f);
        int w = __float2int_ru(kk);
        if (w < 1) w = 1;
        if (w > NROWS) { need_deep = true; break; }
        s_f  = sS[w];
        ys_f = sY[w];
        bb  += bu_tab[w];
        bool stop = (kk > (float)TT) || (kk < k_old);
        k_old = kk;
        if (stop) break;
    }

    if (need_deep) {
        // exact slow path (never taken for these inputs): redo from scratch
        bb = sbeta; k_old = 0.f; s_f = 1.f; ys_f = 0.f;
        for (int it = 0; it < N_ITERS; it++) {
            float kk = fmaf(bb, rt[it], 2.0f);
            int w = __float2int_ru(kk);
            if (w < 1) w = 1;
            float s, bs, ys;
            if (w <= NROWS) {
                s = sS[w]; bs = sB[w]; ys = sY[w];
                bb += bu_tab[w];
            } else {
                if (w > TT) w = TT;
                const float4* u4  = (const float4*)g_u;
                const float4* wv4 = (const float4*)(W + (size_t)(2 * CC) * CC);
                float m_r = neg_inf(), s_r = 0.f, b_r = 0.f, y_r = 0.f;
                for (int l = wid; l < w; l += 8) {
                    if (l == 0) continue;                // masked position
                    const float4* xr = (const float4*)(x + (size_t)(TT - 1 - l) * CC);
                    float du = 0.f, dv = 0.f;
                    for (int c = 0; c < 8; c++) {
                        float4 xa = xr[c * 32 + lane];
                        float4 ub = u4[c * 32 + lane];
                        float4 vb = wv4[c * 32 + lane];
                        du += xa.x * ub.x + xa.y * ub.y + xa.z * ub.z + xa.w * ub.w;
                        dv += xa.x * vb.x + xa.y * vb.y + xa.z * vb.z + xa.w * vb.w;
                    }
                    du = wred_sum(du); dv = wred_sum(dv);
                    float att = du * SCALE;
                    float mn = fmaxf(m_r, att);
                    float ro = __expf(m_r - mn);
                    float e  = __expf(att - mn);
                    s_r = s_r * ro + e;
                    b_r = b_r * ro + e * (float)l;
                    y_r = y_r * ro + e * dv;
                    m_r = mn;
                }
                if (lane == 0) { fm[wid] = m_r; fs[wid] = s_r; fb[wid] = b_r; fy[wid] = y_r; }
                __syncthreads();
                float M = fm[0];
                for (int i = 1; i < 8; i++) M = fmaxf(M, fm[i]);
                s = 0.f; bs = 0.f; ys = 0.f;
                for (int i = 0; i < 8; i++) {
                    float r2 = __expf(fm[i] - M);
                    s  += fs[i] * r2;
                    bs += fb[i] * r2;
                    ys += fy[i] * r2;
                }
                __syncthreads();
                bb += bs / s;
            }
            s_f = s; ys_f = ys;
            bool stop = (kk > (float)TT) || (kk < k_old);
            k_old = kk;
            if (stop) break;
        }
    }

    if (t == 0) out[0] = ys_f / s_f;
}

// ---------------------------------------------------------------------------
extern "C" void kernel_launch(void* const* d_in, const int* in_sizes, int n_in,
                              void* d_out, int out_size) {
    const float* x = nullptr;
    const float* W = nullptr;
    const float* alpha = nullptr;
    const float* beta = nullptr;
    for (int i = 0; i < n_in; i++) {
        if (in_sizes[i] == TT * CC)                x = (const float*)d_in[i];
        else if (in_sizes[i] == (2 * CC + 1) * CC) W = (const float*)d_in[i];
        else if (in_sizes[i] == 1) {
            if (!alpha) alpha = (const float*)d_in[i];
            else        beta  = (const float*)d_in[i];
        }
    }
    float* out = (float*)d_out;
    k_all<<<GRID, NTH>>>(x, W, alpha, beta, out);
}

// round 17
// speedup vs baseline: 1.3525x; 1.3525x over previous
#include <cuda_runtime.h>
#include <cstdint>

#define TT 16384
#define CC 1024
#define NROWS 128           // tail rows in stats table (window provably < 25)
#define N_ITERS 30
#define GRID 144            // <= 148 SMs -> one wave, safe software grid barrier
#define NTH 256
#define NB 64               // stage-B blocks (16 u-columns each)

__device__ float g_q[CC];
__device__ float g_u[CC];             // full u (deep fallback)
__device__ float g_patt[NROWS * NB];  // [l][chunk] partial att dots
__device__ float g_av[NROWS];
__device__ int   g_barc[3 * 32];      // [A, B, av]; left 0 after launch

#define SCALE 3.125e-5f     // 0.001 / sqrt(1024)

__device__ __forceinline__ float neg_inf() { return __int_as_float(0xff800000); }

__device__ __forceinline__ void gbar_arrive(int ph) {
    __syncthreads();
    if (threadIdx.x == 0) {
        __threadfence();
        atomicAdd(&g_barc[ph << 5], 1);
    }
}
__device__ __forceinline__ void gbar_wait(int ph, int count) {
    if (threadIdx.x == 0) {
        while (*(volatile int*)&g_barc[ph << 5] < count) { }
        __threadfence();
    }
    __syncthreads();
}

__device__ __forceinline__ float wred_sum(float v) {
#pragma unroll
    for (int o = 16; o; o >>= 1) v += __shfl_xor_sync(0xffffffffu, v, o);
    return v;
}

__global__ void __launch_bounds__(NTH, 1)
k_all(const float* __restrict__ x, const float* __restrict__ W,
      const float* __restrict__ alpha, const float* __restrict__ beta,
      float* __restrict__ out)
{
    __shared__ float  sq[CC];                  // q in stage B
    __shared__ float4 bred[8][4];              // B u-reduction across warps
    __shared__ float  su[16];                  // this block's u chunk
    __shared__ float  sS[NROWS + 1], sB[NROWS + 1], sY[NROWS + 1];
    __shared__ float  bu_tab[NROWS + 1];
    __shared__ float  tia[32];
    __shared__ float  fm[8], fs[8], fb[8], fy[8];
    __shared__ float  salpha, sbeta;

    const int b = blockIdx.x, t = threadIdx.x;
    const int lane = t & 31, wid = t >> 5;

    if (b == 0 && t == 0) { salpha = *alpha; sbeta = *beta; }

    // ======== STAGE A: q rows (blocks 0-127) || av tail rows (128-143) ========
    if (b < 128) {
        int i = (b << 3) + wid;                       // W_q row
        const float4* xl4 = (const float4*)(x + (size_t)(TT - 1) * CC);
        const float4* wr4 = (const float4*)(W + (size_t)i * CC);
        float4 xa[8], wa[8];
#pragma unroll
        for (int c = 0; c < 8; c++) xa[c] = xl4[c * 32 + lane];
#pragma unroll
        for (int c = 0; c < 8; c++) wa[c] = wr4[c * 32 + lane];
        float s = 0.f;
#pragma unroll
        for (int c = 0; c < 8; c++)
            s += xa[c].x * wa[c].x + xa[c].y * wa[c].y + xa[c].z * wa[c].z + xa[c].w * wa[c].w;
        s = wred_sum(s);
        if (lane == 0) g_q[i] = s;
    } else {
        int l = ((b - 128) << 3) + wid;               // tail distance
        const float4* xr4 = (const float4*)(x + (size_t)(TT - 1 - l) * CC);
        const float4* wv4 = (const float4*)(W + (size_t)(2 * CC) * CC);
        float4 xa[8], wa[8];
#pragma unroll
        for (int c = 0; c < 8; c++) xa[c] = xr4[c * 32 + lane];
#pragma unroll
        for (int c = 0; c < 8; c++) wa[c] = wv4[c * 32 + lane];
        float s = 0.f;
#pragma unroll
        for (int c = 0; c < 8; c++)
            s += xa[c].x * wa[c].x + xa[c].y * wa[c].y + xa[c].z * wa[c].z + xa[c].w * wa[c].w;
        s = wred_sum(s);
        if (lane == 0) g_av[l] = s;
        gbar_arrive(2);                               // av counter
        return;
    }

    // ---- stage-B prefetch (independent of q): this block's W_k column slice --
    // Layout: thread (ig = t>>2, jj4 = t&3) covers rows i = ig + 64*s, cols
    // j0 + 4*jj4 .. +4. Per warp-step: 8 consecutive rows x 64 B contiguous
    // -> all 32-B sectors fully used.
    const int j0  = b << 4;                 // 16 columns per B block
    const int ig  = t >> 2;
    const int jj4 = t & 3;
    float4 wkr[16];
    if (b < NB) {
        const float* Wk = W + (size_t)CC * CC;
#pragma unroll
        for (int s8 = 0; s8 < 16; s8++)
            wkr[s8] = *(const float4*)(Wk + (size_t)(ig + 64 * s8) * CC + j0 + 4 * jj4);
    }
    gbar_arrive(0);                         // A counter
    if (b >= NB) return;                    // blocks 64-127 done

    // patt x-slice load AFTER this block's stage-A issue, overlapping bar0 wait
    float4 xp0, xp1;
    {
        int l = t >> 1, h = t & 1;
        const float4* xr = (const float4*)(x + (size_t)(TT - 1 - l) * CC + j0 + 8 * h);
        xp0 = xr[0]; xp1 = xr[1];
    }
    if (b == 0 && t < N_ITERS) tia[t] = 2.0f / (salpha + (float)t);
    gbar_wait(0, 128);

    // ======== STAGE B (blocks 0-63): exact u chunk + partial att ==============
    {
        ((float4*)sq)[t] = ((const float4*)g_q)[t];   // q from L2
        __syncthreads();
        float4 acc = make_float4(0.f, 0.f, 0.f, 0.f);
#pragma unroll
        for (int s8 = 0; s8 < 16; s8++) {
            float qv = sq[ig + 64 * s8];
            acc.x += qv * wkr[s8].x; acc.y += qv * wkr[s8].y;
            acc.z += qv * wkr[s8].z; acc.w += qv * wkr[s8].w;
        }
        // reduce over ig&7 within warp (lane = (ig&7)*4 + jj4)
#pragma unroll
        for (int o = 4; o < 32; o <<= 1) {
            acc.x += __shfl_xor_sync(0xffffffffu, acc.x, o);
            acc.y += __shfl_xor_sync(0xffffffffu, acc.y, o);
            acc.z += __shfl_xor_sync(0xffffffffu, acc.z, o);
            acc.w += __shfl_xor_sync(0xffffffffu, acc.w, o);
        }
        if (lane < 4) bred[wid][lane] = acc;
        __syncthreads();
        if (t < 4) {
            float4 r = bred[0][t];
#pragma unroll
            for (int w = 1; w < 8; w++) {
                float4 p = bred[w][t];
                r.x += p.x; r.y += p.y; r.z += p.z; r.w += p.w;
            }
            ((float4*)su)[t] = r;
            ((float4*)g_u)[(b << 2) + t] = r;         // for the deep fallback
        }
        __syncthreads();

        // partial att: thread (l = t>>1, h = t&1), x slice already in registers
        int h = t & 1, l = t >> 1;
        float4 u0 = ((float4*)su)[2 * h], u1 = ((float4*)su)[2 * h + 1];
        float d = xp0.x * u0.x + xp0.y * u0.y + xp0.z * u0.z + xp0.w * u0.w
                + xp1.x * u1.x + xp1.y * u1.y + xp1.z * u1.z + xp1.w * u1.w;
        d += __shfl_xor_sync(0xffffffffu, d, 1);
        if (h == 0) g_patt[l * NB + b] = d;
    }
    gbar_arrive(1);                         // B counter
    if (b != 0) return;
    gbar_wait(1, NB);
    gbar_wait(2, 16);                       // av ready (long done)
    if (t == 0) { g_barc[0] = 0; g_barc[32] = 0; g_barc[64] = 0; }   // replay-safe

    // ======== STAGE D (block 0): att assembly + stats + serial recurrence =====
    float v0 = (t < NROWS) ? g_av[t] : 0.f;
    float a0 = neg_inf();
    if (t > 0 && t < NROWS) {
        const float4* pr = (const float4*)(g_patt + t * NB);
        float sum = 0.f;
#pragma unroll
        for (int c = 0; c < NB / 4; c++) {
            float4 p = pr[c];
            sum += p.x + p.y + p.z + p.w;
        }
        a0 = sum * SCALE;
    }

    // stats: att in [-1e-3,1e-3] -> exp safe without max shift (shift-invariant)
    if (t < NROWS) {
        float e0 = __expf(a0);                        // a0 = -inf at t=0 -> 0
        float ps = e0, pb = e0 * (float)t, py = e0 * v0;
#pragma unroll
        for (int o = 1; o < 32; o <<= 1) {
            float ts = __shfl_up_sync(0xffffffffu, ps, o);
            float tb = __shfl_up_sync(0xffffffffu, pb, o);
            float ty = __shfl_up_sync(0xffffffffu, py, o);
            if (lane >= o) { ps += ts; pb += tb; py += ty; }
        }
        if (lane == 31) { fs[wid] = ps; fb[wid] = pb; fy[wid] = py; }
        __syncthreads();
        if (t == 0) {
            float cs = 0.f, cb = 0.f, cy = 0.f;
#pragma unroll
            for (int i = 0; i < 4; i++) {
                float ns = fs[i], nb = fb[i], ny = fy[i];
                fs[i] = cs; fb[i] = cb; fy[i] = cy;
                cs += ns; cb += nb; cy += ny;
            }
        }
        __syncthreads();
        ps += fs[wid]; pb += fb[wid]; py += fy[wid];
        sS[t + 1] = ps; sB[t + 1] = pb; sY[t + 1] = py;
        bu_tab[t + 1] = pb / ps;
        if (t == 0) { sS[0] = 0.f; sB[0] = 0.f; sY[0] = 0.f; bu_tab[0] = 0.f; }
    } else {
        __syncthreads(); __syncthreads();
    }
    __syncthreads();

    // ---- fast serial loop: register tia, fully unrolled -----------------------
    float rt[N_ITERS];
#pragma unroll
    for (int i = 0; i < N_ITERS; i++) rt[i] = tia[i];

    float bb = sbeta, k_old = 0.f;
    float s_f = 1.f, ys_f = 0.f;
    bool need_deep = false;
#pragma unroll
    for (int it = 0; it < N_ITERS; it++) {
        float kk = fmaf(bb, rt[it], 2.0f);
        int w = __float2int_ru(kk);
        if (w < 1) w = 1;
        if (w > NROWS) { need_deep = true; break; }
        s_f  = sS[w];
        ys_f = sY[w];
        bb  += bu_tab[w];
        bool stop = (kk > (float)TT) || (kk < k_old);
        k_old = kk;
        if (stop) break;
    }

    if (need_deep) {
        // exact slow path (never taken for these inputs): redo from scratch
        bb = sbeta; k_old = 0.f; s_f = 1.f; ys_f = 0.f;
        for (int it = 0; it < N_ITERS; it++) {
            float kk = fmaf(bb, rt[it], 2.0f);
            int w = __float2int_ru(kk);
            if (w < 1) w = 1;
            float s, bs, ys;
            if (w <= NROWS) {
                s = sS[w]; bs = sB[w]; ys = sY[w];
                bb += bu_tab[w];
            } else {
                if (w > TT) w = TT;
                const float4* u4  = (const float4*)g_u;
                const float4* wv4 = (const float4*)(W + (size_t)(2 * CC) * CC);
                float m_r = neg_inf(), s_r = 0.f, b_r = 0.f, y_r = 0.f;
                for (int l = wid; l < w; l += 8) {
                    if (l == 0) continue;                // masked position
                    const float4* xr = (const float4*)(x + (size_t)(TT - 1 - l) * CC);
                    float du = 0.f, dv = 0.f;
                    for (int c = 0; c < 8; c++) {
                        float4 xa = xr[c * 32 + lane];
                        float4 ub = u4[c * 32 + lane];
                        float4 vb = wv4[c * 32 + lane];
                        du += xa.x * ub.x + xa.y * ub.y + xa.z * ub.z + xa.w * ub.w;
                        dv += xa.x * vb.x + xa.y * vb.y + xa.z * vb.z + xa.w * vb.w;
                    }
                    du = wred_sum(du); dv = wred_sum(dv);
                    float att = du * SCALE;
                    float mn = fmaxf(m_r, att);
                    float ro = __expf(m_r - mn);
                    float e  = __expf(att - mn);
                    s_r = s_r * ro + e;
                    b_r = b_r * ro + e * (float)l;
                    y_r = y_r * ro + e * dv;
                    m_r = mn;
                }
                if (lane == 0) { fm[wid] = m_r; fs[wid] = s_r; fb[wid] = b_r; fy[wid] = y_r; }
                __syncthreads();
                float M = fm[0];
                for (int i = 1; i < 8; i++) M = fmaxf(M, fm[i]);
                s = 0.f; bs = 0.f; ys = 0.f;
                for (int i = 0; i < 8; i++) {
                    float r2 = __expf(fm[i] - M);
                    s  += fs[i] * r2;
                    bs += fb[i] * r2;
                    ys += fy[i] * r2;
                }
                __syncthreads();
                bb += bs / s;
            }
            s_f = s; ys_f = ys;
            bool stop = (kk > (float)TT) || (kk < k_old);
            k_old = kk;
            if (stop) break;
        }
    }

    if (t == 0) out[0] = ys_f / s_f;
}

// ---------------------------------------------------------------------------
extern "C" void kernel_launch(void* const* d_in, const int* in_sizes, int n_in,
                              void* d_out, int out_size) {
    const float* x = nullptr;
    const float* W = nullptr;
    const float* alpha = nullptr;
    const float* beta = nullptr;
    for (int i = 0; i < n_in; i++) {
        if (in_sizes[i] == TT * CC)                x = (const float*)d_in[i];
        else if (in_sizes[i] == (2 * CC + 1) * CC) W = (const float*)d_in[i];
        else if (in_sizes[i] == 1) {
            if (!alpha) alpha = (const float*)d_in[i];
            else        beta  = (const float*)d_in[i];
        }
    }
    float* out = (float*)d_out;
    k_all<<<GRID, NTH>>>(x, W, alpha, beta, out);
}